// round 5
// baseline (speedup 1.0000x reference)
#include <cuda_runtime.h>
#include <cstdint>

typedef unsigned int u32;
typedef unsigned long long u64;

#define S_LEN   1024
#define D_DIM   64
#define CHUNK   64
#define NCHUNK  16
#define THREADS 256

// smem (bytes)
#define QH_OFF   0
#define QL_OFF   16384
#define B0_OFF   32768     // per-buffer: KH 0 | KL 8K | VH 16K | VL 24K ; stride 32K
#define RINV_OFF 98304     // 128 floats
#define SM_TOTAL 98816

__device__ __forceinline__ u32 smem_u32(const void* p) {
    u32 a;
    asm("{ .reg .u64 t; cvta.to.shared.u64 t, %1; cvt.u32.u64 %0, t; }"
        : "=r"(a) : "l"(p));
    return a;
}
__device__ __forceinline__ u32 swz(u32 b) { return b ^ ((b >> 3) & 0x70); }

// split two floats -> packed bf16x2 hi word + bf16x2 residual word (lo = first arg)
__device__ __forceinline__ void split2(float a, float b, u32& hw, u32& lw) {
    asm("cvt.rn.bf16x2.f32 %0, %1, %2;" : "=r"(hw) : "f"(b), "f"(a));
    float af  = __uint_as_float(hw << 16);
    float bf_ = __uint_as_float(hw & 0xffff0000u);
    asm("cvt.rn.bf16x2.f32 %0, %1, %2;" : "=r"(lw) : "f"(b - bf_), "f"(a - af));
}

#define LDSM4(r0,r1,r2,r3,addr) \
    asm volatile("ldmatrix.sync.aligned.m8n8.x4.shared.b16 {%0,%1,%2,%3}, [%4];" \
        : "=r"(r0),"=r"(r1),"=r"(r2),"=r"(r3) : "r"(addr))
#define LDSM4T(r0,r1,r2,r3,addr) \
    asm volatile("ldmatrix.sync.aligned.m8n8.x4.trans.shared.b16 {%0,%1,%2,%3}, [%4];" \
        : "=r"(r0),"=r"(r1),"=r"(r2),"=r"(r3) : "r"(addr))
#define MMA(c,a0,a1,a2,a3,b0,b1) \
    asm volatile("mma.sync.aligned.m16n8k16.row.col.f32.bf16.bf16.f32 " \
        "{%0,%1,%2,%3},{%4,%5,%6,%7},{%8,%9},{%0,%1,%2,%3};" \
        : "+f"((c)[0]),"+f"((c)[1]),"+f"((c)[2]),"+f"((c)[3]) \
        : "r"(a0),"r"(a1),"r"(a2),"r"(a3),"r"(b0),"r"(b1))

__device__ __forceinline__ void stage_q(char* smem, const float* qb, int tid) {
    for (int it = tid; it < 2048; it += THREADS) {
        int r = it >> 4, d4 = it & 15;
        float4 v = *(const float4*)(qb + r * 64 + d4 * 4);
        u32 h0, l0, h1, l1;
        split2(v.x, v.y, h0, l0);
        split2(v.z, v.w, h1, l1);
        u32 o = swz((u32)(r * 128 + d4 * 8));
        *(u64*)(smem + QH_OFF + o) = ((u64)h1 << 32) | h0;
        *(u64*)(smem + QL_OFF + o) = ((u64)l1 << 32) | l0;
    }
}

// stage one 64-col k chunk + one 64-row v chunk into buffer `buf`
__device__ __forceinline__ void stage_kv(char* smem, const float* kc,
                                         const float* vc, int buf, int tid) {
    char* base = smem + B0_OFF + buf * 32768;
    // k: gmem [d][s] -> smem [s][d] bf16 hi/lo (64 rows x 128B)
    for (int it = tid; it < 512; it += THREADS) {
        int d2 = it >> 4, s4 = it & 15;
        const float* p0 = kc + (long)(2 * d2) * S_LEN + s4 * 4;
        float4 ka = *(const float4*)p0;
        float4 kb = *(const float4*)(p0 + S_LEN);
        float av[4] = {ka.x, ka.y, ka.z, ka.w};
        float bv[4] = {kb.x, kb.y, kb.z, kb.w};
        #pragma unroll
        for (int j = 0; j < 4; j++) {
            int row = s4 * 4 + j;
            u32 h, l;
            split2(av[j], bv[j], h, l);
            u32 o = swz((u32)(row * 128 + d2 * 4));
            *(u32*)(base + o) = h;           // KH
            *(u32*)(base + 8192 + o) = l;    // KL
        }
    }
    // v: gmem [s][d] -> smem [s][d] bf16 hi/lo (64 rows x 128B)
    for (int it = tid; it < 1024; it += THREADS) {
        int r = it >> 4, d4 = it & 15;
        float4 v = *(const float4*)(vc + r * 64 + d4 * 4);
        u32 h0, l0, h1, l1;
        split2(v.x, v.y, h0, l0);
        split2(v.z, v.w, h1, l1);
        u32 o = swz((u32)(r * 128 + d4 * 8));
        *(u64*)(base + 16384 + o) = ((u64)h1 << 32) | h0;   // VH
        *(u64*)(base + 24576 + o) = ((u64)l1 << 32) | l0;   // VL
    }
}

__global__ void __launch_bounds__(THREADS, 2)
attn_fused(const float* __restrict__ qg,    const float* __restrict__ kg,
           const float* __restrict__ vg,    const float* __restrict__ prevg,
           const float* __restrict__ maskg, const float* __restrict__ scaleg,
           float* __restrict__ outg, float* __restrict__ woutg,
           float* __restrict__ soutg)
{
    extern __shared__ char smem[];
    const u32 sb  = smem_u32(smem);
    const int tid = threadIdx.x, wid = tid >> 5, lid = tid & 31;
    const int bh  = blockIdx.x >> 3;
    const int q0  = (blockIdx.x & 7) << 7;
    const int qw  = wid << 4;

    const float sc = *scaleg;
    float* rinv = (float*)(smem + RINV_OFF);

    const float* kbh = kg + (long)bh * D_DIM * S_LEN;
    const float* vbh = vg + (long)bh * S_LEN * D_DIM;

    stage_q(smem, qg + ((long)bh * S_LEN + q0) * D_DIM, tid);
    stage_kv(smem, kbh, vbh, 0, tid);
    __syncthreads();

    // persistent A (q) hi fragments
    u32 ah[4][4];
    const u32 aq = (u32)((qw + (lid & 15)) * 128 + (lid >> 4) * 16);
    #pragma unroll
    for (int ks = 0; ks < 4; ks++)
        LDSM4(ah[ks][0], ah[ks][1], ah[ks][2], ah[ks][3],
              sb + QH_OFF + swz(aq + ks * 32));

    const int  rl   = lid >> 2;
    const int  cb   = 2 * (lid & 3);
    const long rglo = q0 + qw + rl;
    const long rghi = rglo + 8;

    const u32 brow = (u32)((lid & 7) + ((lid >> 4) << 3));
    const u32 bcol = (u32)(((lid >> 3) & 1) << 3);
    const u32 vrow = (u32)((lid & 7) + (((lid >> 3) & 1) << 3));
    const u32 vcol = (u32)((lid >> 4) << 3);

    float out2[8][4];
    #pragma unroll
    for (int nt = 0; nt < 8; nt++)
        { out2[nt][0]=0.f; out2[nt][1]=0.f; out2[nt][2]=0.f; out2[nt][3]=0.f; }
    float s_lo = 0.f, s_hi = 0.f;

    for (int c = 0; c < NCHUNK; c++) {
        if (c < NCHUNK - 1)
            stage_kv(smem, kbh + (c + 1) * CHUNK,
                     vbh + (long)(c + 1) * CHUNK * D_DIM, (c + 1) & 1, tid);

        const char* base = smem + B0_OFF + (c & 1) * 32768;
        const u32 kh = sb + B0_OFF + (u32)((c & 1) * 32768);
        const u32 kl = kh + 8192;
        const u32 vh = kh + 16384;
        const u32 vl = kh + 24576;
        (void)base;

        // ---- QK for this 64-col chunk ----
        float acc[8][4];
        #pragma unroll
        for (int nt = 0; nt < 8; nt++)
            { acc[nt][0]=0.f; acc[nt][1]=0.f; acc[nt][2]=0.f; acc[nt][3]=0.f; }

        #pragma unroll
        for (int ks = 0; ks < 4; ks++) {
            u32 al0, al1, al2, al3;
            LDSM4(al0, al1, al2, al3, sb + QL_OFF + swz(aq + ks * 32));
            #pragma unroll
            for (int np = 0; np < 4; np++) {
                u32 off = swz((u32)((np * 16 + brow) * 128 + (ks * 16 + bcol) * 2));
                u32 h0, h1, h2, h3, l0, l1, l2, l3;
                LDSM4(h0, h1, h2, h3, kh + off);
                LDSM4(l0, l1, l2, l3, kl + off);
                MMA(acc[2*np],   ah[ks][0],ah[ks][1],ah[ks][2],ah[ks][3], h0, h1);
                MMA(acc[2*np+1], ah[ks][0],ah[ks][1],ah[ks][2],ah[ks][3], h2, h3);
                MMA(acc[2*np],   ah[ks][0],ah[ks][1],ah[ks][2],ah[ks][3], l0, l1);
                MMA(acc[2*np+1], ah[ks][0],ah[ks][1],ah[ks][2],ah[ks][3], l2, l3);
                MMA(acc[2*np],   al0,al1,al2,al3, h0, h1);
                MMA(acc[2*np+1], al0,al1,al2,al3, h2, h3);
            }
        }

        // ---- epilogue: s = a*mask*sc + prev; write s; p = exp(s) in place ----
        const float* mplo = maskg + rglo * S_LEN + c * CHUNK + cb;
        const float* mphi = maskg + rghi * S_LEN + c * CHUNK + cb;
        const float* pplo = prevg + ((long)bh * S_LEN + rglo) * S_LEN + c * CHUNK + cb;
        const float* pphi = prevg + ((long)bh * S_LEN + rghi) * S_LEN + c * CHUNK + cb;
        float* splo = soutg + ((long)bh * S_LEN + rglo) * S_LEN + c * CHUNK + cb;
        float* sphi = soutg + ((long)bh * S_LEN + rghi) * S_LEN + c * CHUNK + cb;

        #pragma unroll
        for (int nt = 0; nt < 8; nt++) {
            const int so = nt * 8;
            float2 ml = *(const float2*)(mplo + so);
            float2 mh = *(const float2*)(mphi + so);
            float2 pl = *(const float2*)(pplo + so);
            float2 ph = *(const float2*)(pphi + so);
            float v0 = acc[nt][0] * ml.x * sc + pl.x;
            float v1 = acc[nt][1] * ml.y * sc + pl.y;
            float v2 = acc[nt][2] * mh.x * sc + ph.x;
            float v3 = acc[nt][3] * mh.y * sc + ph.y;
            float2 olo = {v0, v1}, ohi = {v2, v3};
            *(float2*)(splo + so) = olo;
            *(float2*)(sphi + so) = ohi;
            float p0 = __expf(v0), p1 = __expf(v1);
            float p2 = __expf(v2), p3 = __expf(v3);
            acc[nt][0] = p0; acc[nt][1] = p1; acc[nt][2] = p2; acc[nt][3] = p3;
            s_lo += p0 + p1;
            s_hi += p2 + p3;
        }

        // ---- AV: out2 += P (from regs, split hi/lo) x V ----
        #pragma unroll
        for (int t = 0; t < 4; t++) {
            u32 a0, a1, a2, a3, e0, e1, e2, e3;
            split2(acc[2*t][0],   acc[2*t][1],   a0, e0);
            split2(acc[2*t][2],   acc[2*t][3],   a1, e1);
            split2(acc[2*t+1][0], acc[2*t+1][1], a2, e2);
            split2(acc[2*t+1][2], acc[2*t+1][3], a3, e3);
            #pragma unroll
            for (int dp = 0; dp < 4; dp++) {
                u32 off = swz((u32)((t * 16 + vrow) * 128 + (dp * 16 + vcol) * 2));
                u32 h0, h1, h2, h3, l0, l1, l2, l3;
                LDSM4T(h0, h1, h2, h3, vh + off);
                LDSM4T(l0, l1, l2, l3, vl + off);
                MMA(out2[2*dp],   a0,a1,a2,a3, h0, h1);
                MMA(out2[2*dp+1], a0,a1,a2,a3, h2, h3);
                MMA(out2[2*dp],   a0,a1,a2,a3, l0, l1);
                MMA(out2[2*dp+1], a0,a1,a2,a3, l2, l3);
                MMA(out2[2*dp],   e0,e1,e2,e3, h0, h1);
                MMA(out2[2*dp+1], e0,e1,e2,e3, h2, h3);
            }
        }
        __syncthreads();
    }

    // ---- row sums -> inv ----
    s_lo += __shfl_xor_sync(0xffffffffu, s_lo, 1);
    s_lo += __shfl_xor_sync(0xffffffffu, s_lo, 2);
    s_hi += __shfl_xor_sync(0xffffffffu, s_hi, 1);
    s_hi += __shfl_xor_sync(0xffffffffu, s_hi, 2);
    if ((lid & 3) == 0) {
        rinv[qw + rl]     = 1.0f / s_lo;
        rinv[qw + rl + 8] = 1.0f / s_hi;
    }
    __syncthreads();

    // ---- output = out2 * inv ----
    {
        const float inv_lo = rinv[qw + rl];
        const float inv_hi = rinv[qw + rl + 8];
        float* olo = outg + ((long)bh * S_LEN + rglo) * D_DIM + cb;
        float* ohi = outg + ((long)bh * S_LEN + rghi) * D_DIM + cb;
        #pragma unroll
        for (int nt = 0; nt < 8; nt++) {
            float2 a = {out2[nt][0] * inv_lo, out2[nt][1] * inv_lo};
            float2 b = {out2[nt][2] * inv_hi, out2[nt][3] * inv_hi};
            __stcs((float2*)(olo + nt * 8), a);
            __stcs((float2*)(ohi + nt * 8), b);
        }
    }

    // ---- weights pass: fully coalesced stream, w = exp(s) * inv ----
    for (int r = 0; r < 16; r++) {
        const int row = qw + r;
        const float inv = rinv[row];
        const float* srow = soutg + ((long)bh * S_LEN + q0 + row) * S_LEN;
        float*       wrow = woutg + ((long)bh * S_LEN + q0 + row) * S_LEN;
        #pragma unroll
        for (int j = 0; j < 8; j++) {
            const int idx = j * 128 + lid * 4;
            float4 s = *(const float4*)(srow + idx);
            float4 w;
            w.x = __expf(s.x) * inv;
            w.y = __expf(s.y) * inv;
            w.z = __expf(s.z) * inv;
            w.w = __expf(s.w) * inv;
            __stcs((float4*)(wrow + idx), w);
        }
    }
}

extern "C" void kernel_launch(void* const* d_in, const int* in_sizes, int n_in,
                              void* d_out, int out_size) {
    const float* q     = (const float*)d_in[0];
    const float* k     = (const float*)d_in[1];
    const float* v     = (const float*)d_in[2];
    const float* prev  = (const float*)d_in[3];
    const float* mask  = (const float*)d_in[4];
    const float* scale = (const float*)d_in[5];

    float* out  = (float*)d_out;
    float* wout = out  + (long)8 * 16 * 1024 * 64;
    float* sout = wout + (long)8 * 16 * 1024 * 1024;

    cudaFuncSetAttribute(attn_fused,
                         cudaFuncAttributeMaxDynamicSharedMemorySize, SM_TOTAL);
    attn_fused<<<8 * 16 * 8, THREADS, SM_TOTAL>>>(
        q, k, v, prev, mask, scale, out, wout, sout);
}

// round 7
// speedup vs baseline: 1.2642x; 1.2642x over previous
#include <cuda_runtime.h>
#include <cstdint>

typedef unsigned int u32;
typedef unsigned long long u64;

#define S_LEN   1024
#define D_DIM   64
#define CHUNK   32
#define NCHUNK  32
#define THREADS 256

// smem layout (bytes)
// prologue: Q staging [0,32K) (QH 0, QL 16K) -- dead after fragment load
// steady:   PREV [0,20480) rows 128 x 160B ; MASK [20480,40960)
//           KV buffers [40960, 40960+2*16384): per buf KH|KL|VH|VL 4K each
#define QH_OFF   0
#define QL_OFF   16384
#define PREV_OFF 0
#define MASK_OFF 20480
#define KV_OFF   40960
#define RINV_OFF 73728
#define SM_TOTAL 74240

#define MPROW 160   // bytes per staged mask/prev row (40 floats, 16B-aligned, 2-way max)

__device__ __forceinline__ u32 smem_u32(const void* p) {
    u32 a;
    asm("{ .reg .u64 t; cvta.to.shared.u64 t, %1; cvt.u32.u64 %0, t; }"
        : "=r"(a) : "l"(p));
    return a;
}
__device__ __forceinline__ u32 swz(u32 b) { return b ^ ((b >> 3) & 0x70); }

__device__ __forceinline__ void split2(float a, float b, u32& hw, u32& lw) {
    asm("cvt.rn.bf16x2.f32 %0, %1, %2;" : "=r"(hw) : "f"(b), "f"(a));
    float af  = __uint_as_float(hw << 16);
    float bf_ = __uint_as_float(hw & 0xffff0000u);
    asm("cvt.rn.bf16x2.f32 %0, %1, %2;" : "=r"(lw) : "f"(b - bf_), "f"(a - af));
}

#define LDSM4(r0,r1,r2,r3,addr) \
    asm volatile("ldmatrix.sync.aligned.m8n8.x4.shared.b16 {%0,%1,%2,%3}, [%4];" \
        : "=r"(r0),"=r"(r1),"=r"(r2),"=r"(r3) : "r"(addr))
#define LDSM4T(r0,r1,r2,r3,addr) \
    asm volatile("ldmatrix.sync.aligned.m8n8.x4.trans.shared.b16 {%0,%1,%2,%3}, [%4];" \
        : "=r"(r0),"=r"(r1),"=r"(r2),"=r"(r3) : "r"(addr))
#define MMA(c,a0,a1,a2,a3,b0,b1) \
    asm volatile("mma.sync.aligned.m16n8k16.row.col.f32.bf16.bf16.f32 " \
        "{%0,%1,%2,%3},{%4,%5,%6,%7},{%8,%9},{%0,%1,%2,%3};" \
        : "+f"((c)[0]),"+f"((c)[1]),"+f"((c)[2]),"+f"((c)[3]) \
        : "r"(a0),"r"(a1),"r"(a2),"r"(a3),"r"(b0),"r"(b1))

#define CP16(saddr, gptr) \
    asm volatile("cp.async.cg.shared.global [%0], [%1], 16;" \
        :: "r"(saddr), "l"(gptr) : "memory")
#define CP_COMMIT() asm volatile("cp.async.commit_group;" ::: "memory")
#define CP_WAIT0()  asm volatile("cp.async.wait_group 0;" ::: "memory")

__device__ __forceinline__ void stage_q(char* smem, const float* qb, int tid) {
    for (int it = tid; it < 2048; it += THREADS) {
        int r = it >> 4, d4 = it & 15;
        float4 v = *(const float4*)(qb + r * 64 + d4 * 4);
        u32 h0, l0, h1, l1;
        split2(v.x, v.y, h0, l0);
        split2(v.z, v.w, h1, l1);
        u32 o = swz((u32)(r * 128 + d4 * 8));
        *(u64*)(smem + QH_OFF + o) = ((u64)h1 << 32) | h0;
        *(u64*)(smem + QL_OFF + o) = ((u64)l1 << 32) | l0;
    }
}

__global__ void __launch_bounds__(THREADS, 2)
attn_fused(const float* __restrict__ qg,    const float* __restrict__ kg,
           const float* __restrict__ vg,    const float* __restrict__ prevg,
           const float* __restrict__ maskg, const float* __restrict__ scaleg,
           float* __restrict__ outg, float* __restrict__ woutg,
           float* __restrict__ soutg)
{
    extern __shared__ char smem[];
    const u32 sb  = smem_u32(smem);
    const int tid = threadIdx.x, wid = tid >> 5, lid = tid & 31;
    const int bh  = blockIdx.x >> 3;
    const int q0  = (blockIdx.x & 7) << 7;
    const int qw  = wid << 4;

    const float sc = *scaleg;
    float* rinv = (float*)(smem + RINV_OFF);

    const float* kbh = kg + (long)bh * D_DIM * S_LEN;
    const float* vbh = vg + (long)bh * S_LEN * D_DIM;
    const float* pbh = prevg + (long)bh * S_LEN * S_LEN;

    // ---- prologue: q fragments + chunk-0 kv staging ----
    stage_q(smem, qg + ((long)bh * S_LEN + q0) * D_DIM, tid);
    // stage kv chunk 0 (buffer 0) directly
    {
        char* base = smem + KV_OFF;
        int d2 = tid >> 3, s4 = tid & 7;
        const float* p0 = kbh + (long)(2 * d2) * S_LEN + s4 * 4;
        float4 ka = *(const float4*)p0;
        float4 kb = *(const float4*)(p0 + S_LEN);
        float av[4] = {ka.x, ka.y, ka.z, ka.w};
        float bv[4] = {kb.x, kb.y, kb.z, kb.w};
        #pragma unroll
        for (int j = 0; j < 4; j++) {
            u32 h, l;
            split2(av[j], bv[j], h, l);
            u32 o = swz((u32)((s4 * 4 + j) * 128 + d2 * 4));
            *(u32*)(base + o) = h;
            *(u32*)(base + 4096 + o) = l;
        }
        #pragma unroll
        for (int i = 0; i < 2; i++) {
            int item = tid + i * 256;
            int r = item >> 4, d4 = item & 15;
            float4 v = *(const float4*)(vbh + (long)r * 64 + d4 * 4);
            u32 h0, l0, h1, l1;
            split2(v.x, v.y, h0, l0);
            split2(v.z, v.w, h1, l1);
            u32 o = swz((u32)(r * 128 + d4 * 8));
            *(u64*)(base + 8192  + o) = ((u64)h1 << 32) | h0;
            *(u64*)(base + 12288 + o) = ((u64)l1 << 32) | l0;
        }
    }
    __syncthreads();

    // persistent q fragments (hi + lo) -> Q smem region becomes free
    u32 ah[4][4], al[4][4];
    const u32 aq = (u32)((qw + (lid & 15)) * 128 + (lid >> 4) * 16);
    #pragma unroll
    for (int ks = 0; ks < 4; ks++) {
        LDSM4(ah[ks][0], ah[ks][1], ah[ks][2], ah[ks][3],
              sb + QH_OFF + swz(aq + ks * 32));
        LDSM4(al[ks][0], al[ks][1], al[ks][2], al[ks][3],
              sb + QL_OFF + swz(aq + ks * 32));
    }
    __syncthreads();

    const int  rl   = lid >> 2;
    const int  cb   = 2 * (lid & 3);
    const long rglo = q0 + qw + rl;
    const long rghi = rglo + 8;

    const u32 brow = (u32)((lid & 7) + ((lid >> 4) << 3));
    const u32 bcol = (u32)(((lid >> 3) & 1) << 3);
    const u32 vrow = (u32)((lid & 7) + (((lid >> 3) & 1) << 3));
    const u32 vcol = (u32)((lid >> 4) << 3);

    float out2[8][4];
    #pragma unroll
    for (int nt = 0; nt < 8; nt++)
        { out2[nt][0]=0.f; out2[nt][1]=0.f; out2[nt][2]=0.f; out2[nt][3]=0.f; }
    float s_lo = 0.f, s_hi = 0.f;

    // per-thread cp.async coords: idx = tid + i*256 ; row = idx>>3 ; j16 = idx&7
    const int cprow = tid >> 3;           // rows advance by 32 per i-step
    const int cpj   = tid & 7;

    for (int c = 0; c < NCHUNK; c++) {
        // ---- (1) cp.async mask+prev tiles for this chunk ----
        {
            const long gco = (long)c * CHUNK + cpj * 4;
            #pragma unroll
            for (int i = 0; i < 4; i++) {
                int r = cprow + i * 32;
                CP16(sb + PREV_OFF + (u32)(r * MPROW + cpj * 16),
                     pbh + (long)(q0 + r) * S_LEN + gco);
            }
            #pragma unroll
            for (int i = 0; i < 4; i++) {
                int r = cprow + i * 32;
                CP16(sb + MASK_OFF + (u32)(r * MPROW + cpj * 16),
                     maskg + (long)(q0 + r) * S_LEN + gco);
            }
            CP_COMMIT();
        }

        // ---- (2) kv gmem loads for chunk c+1 (regs only; overlap with QK) ----
        float4 ka, kb, v0, v1;
        const int d2 = tid >> 3, s4 = tid & 7;
        if (c < NCHUNK - 1) {
            const float* kp = kbh + (long)(2 * d2) * S_LEN + (c + 1) * CHUNK + s4 * 4;
            ka = *(const float4*)kp;
            kb = *(const float4*)(kp + S_LEN);
            const float* vp = vbh + (long)((c + 1) * CHUNK) * 64;
            v0 = *(const float4*)(vp + (long)(tid >> 4) * 64 + (tid & 15) * 4);
            v1 = *(const float4*)(vp + (long)((tid + 256) >> 4) * 64 + (tid & 15) * 4);
        }

        const u32 kvb = sb + KV_OFF + (u32)((c & 1) * 16384);
        const u32 kh = kvb, kl = kvb + 4096, vh = kvb + 8192, vl = kvb + 12288;

        // ---- (3) QK MMAs for chunk c ----
        float acc[4][4];
        #pragma unroll
        for (int nt = 0; nt < 4; nt++)
            { acc[nt][0]=0.f; acc[nt][1]=0.f; acc[nt][2]=0.f; acc[nt][3]=0.f; }

        #pragma unroll
        for (int ks = 0; ks < 4; ks++) {
            #pragma unroll
            for (int np = 0; np < 2; np++) {
                u32 off = swz((u32)((np * 16 + brow) * 128 + (ks * 16 + bcol) * 2));
                u32 h0, h1, h2, h3, l0, l1, l2, l3;
                LDSM4(h0, h1, h2, h3, kh + off);
                LDSM4(l0, l1, l2, l3, kl + off);
                MMA(acc[2*np],   ah[ks][0],ah[ks][1],ah[ks][2],ah[ks][3], h0, h1);
                MMA(acc[2*np+1], ah[ks][0],ah[ks][1],ah[ks][2],ah[ks][3], h2, h3);
                MMA(acc[2*np],   ah[ks][0],ah[ks][1],ah[ks][2],ah[ks][3], l0, l1);
                MMA(acc[2*np+1], ah[ks][0],ah[ks][1],ah[ks][2],ah[ks][3], l2, l3);
                MMA(acc[2*np],   al[ks][0],al[ks][1],al[ks][2],al[ks][3], h0, h1);
                MMA(acc[2*np+1], al[ks][0],al[ks][1],al[ks][2],al[ks][3], h2, h3);
            }
        }

        // ---- (4) kv split + store for chunk c+1 (other buffer) ----
        if (c < NCHUNK - 1) {
            char* nb = smem + KV_OFF + ((c + 1) & 1) * 16384;
            float av[4] = {ka.x, ka.y, ka.z, ka.w};
            float bv[4] = {kb.x, kb.y, kb.z, kb.w};
            #pragma unroll
            for (int j = 0; j < 4; j++) {
                u32 h, l;
                split2(av[j], bv[j], h, l);
                u32 o = swz((u32)((s4 * 4 + j) * 128 + d2 * 4));
                *(u32*)(nb + o) = h;
                *(u32*)(nb + 4096 + o) = l;
            }
            u32 h0, l0, h1, l1;
            split2(v0.x, v0.y, h0, l0);
            split2(v0.z, v0.w, h1, l1);
            u32 o = swz((u32)((tid >> 4) * 128 + (tid & 15) * 8));
            *(u64*)(nb + 8192  + o) = ((u64)h1 << 32) | h0;
            *(u64*)(nb + 12288 + o) = ((u64)l1 << 32) | l0;
            split2(v1.x, v1.y, h0, l0);
            split2(v1.z, v1.w, h1, l1);
            o = swz((u32)(((tid + 256) >> 4) * 128 + (tid & 15) * 8));
            *(u64*)(nb + 8192  + o) = ((u64)h1 << 32) | h0;
            *(u64*)(nb + 12288 + o) = ((u64)l1 << 32) | l0;
        }

        // ---- (5) mask/prev staged; visible to all ----
        CP_WAIT0();
        __syncthreads();

        // ---- (6) epilogue: s = a*mask*sc + prev; STG scores; p = exp(s) ----
        const char* pmlo = smem + PREV_OFF + (qw + rl) * MPROW + cb * 4;
        const char* pmhi = pmlo + 8 * MPROW;
        const char* mmlo = smem + MASK_OFF + (qw + rl) * MPROW + cb * 4;
        const char* mmhi = mmlo + 8 * MPROW;
        float* splo = soutg + ((long)bh * S_LEN + rglo) * S_LEN + c * CHUNK + cb;
        float* sphi = soutg + ((long)bh * S_LEN + rghi) * S_LEN + c * CHUNK + cb;

        #pragma unroll
        for (int nt = 0; nt < 4; nt++) {
            const int so = nt * 8;
            float2 ml = *(const float2*)(mmlo + so * 4);
            float2 mh = *(const float2*)(mmhi + so * 4);
            float2 pl = *(const float2*)(pmlo + so * 4);
            float2 ph = *(const float2*)(pmhi + so * 4);
            float x0 = acc[nt][0] * ml.x * sc + pl.x;
            float x1 = acc[nt][1] * ml.y * sc + pl.y;
            float x2 = acc[nt][2] * mh.x * sc + ph.x;
            float x3 = acc[nt][3] * mh.y * sc + ph.y;
            float2 olo = {x0, x1}, ohi = {x2, x3};
            *(float2*)(splo + so) = olo;
            *(float2*)(sphi + so) = ohi;
            float p0 = __expf(x0), p1 = __expf(x1);
            float p2 = __expf(x2), p3 = __expf(x3);
            acc[nt][0] = p0; acc[nt][1] = p1; acc[nt][2] = p2; acc[nt][3] = p3;
            s_lo += p0 + p1;
            s_hi += p2 + p3;
        }

        // ---- (7) AV: out2 += P x V ----
        #pragma unroll
        for (int t = 0; t < 2; t++) {
            u32 a0, a1, a2, a3, e0, e1, e2, e3;
            split2(acc[2*t][0],   acc[2*t][1],   a0, e0);
            split2(acc[2*t][2],   acc[2*t][3],   a1, e1);
            split2(acc[2*t+1][0], acc[2*t+1][1], a2, e2);
            split2(acc[2*t+1][2], acc[2*t+1][3], a3, e3);
            #pragma unroll
            for (int dp = 0; dp < 4; dp++) {
                u32 off = swz((u32)((t * 16 + vrow) * 128 + (dp * 16 + vcol) * 2));
                u32 h0, h1, h2, h3, l0, l1, l2, l3;
                LDSM4T(h0, h1, h2, h3, vh + off);
                LDSM4T(l0, l1, l2, l3, vl + off);
                MMA(out2[2*dp],   a0,a1,a2,a3, h0, h1);
                MMA(out2[2*dp+1], a0,a1,a2,a3, h2, h3);
                MMA(out2[2*dp],   a0,a1,a2,a3, l0, l1);
                MMA(out2[2*dp+1], a0,a1,a2,a3, l2, l3);
                MMA(out2[2*dp],   e0,e1,e2,e3, h0, h1);
                MMA(out2[2*dp+1], e0,e1,e2,e3, h2, h3);
            }
        }
        // ---- (8) guard mp overwrite + kv buffer rotation ----
        __syncthreads();
    }

    // ---- row sums -> inv ----
    s_lo += __shfl_xor_sync(0xffffffffu, s_lo, 1);
    s_lo += __shfl_xor_sync(0xffffffffu, s_lo, 2);
    s_hi += __shfl_xor_sync(0xffffffffu, s_hi, 1);
    s_hi += __shfl_xor_sync(0xffffffffu, s_hi, 2);
    if ((lid & 3) == 0) {
        rinv[qw + rl]     = 1.0f / s_lo;
        rinv[qw + rl + 8] = 1.0f / s_hi;
    }
    __syncthreads();

    // ---- output = out2 * inv ----
    {
        const float inv_lo = rinv[qw + rl];
        const float inv_hi = rinv[qw + rl + 8];
        float* olo = outg + ((long)bh * S_LEN + rglo) * D_DIM + cb;
        float* ohi = outg + ((long)bh * S_LEN + rghi) * D_DIM + cb;
        #pragma unroll
        for (int nt = 0; nt < 8; nt++) {
            float2 a = {out2[nt][0] * inv_lo, out2[nt][1] * inv_lo};
            float2 b = {out2[nt][2] * inv_hi, out2[nt][3] * inv_hi};
            __stcs((float2*)(olo + nt * 8), a);
            __stcs((float2*)(ohi + nt * 8), b);
        }
    }

    // ---- weights pass: coalesced stream, w = exp(s) * inv ----
    for (int r = 0; r < 16; r++) {
        const int row = qw + r;
        const float inv = rinv[row];
        const float* srow = soutg + ((long)bh * S_LEN + q0 + row) * S_LEN;
        float*       wrow = woutg + ((long)bh * S_LEN + q0 + row) * S_LEN;
        #pragma unroll
        for (int j = 0; j < 8; j++) {
            const int idx = j * 128 + lid * 4;
            float4 s = *(const float4*)(srow + idx);
            float4 w;
            w.x = __expf(s.x) * inv;
            w.y = __expf(s.y) * inv;
            w.z = __expf(s.z) * inv;
            w.w = __expf(s.w) * inv;
            __stcs((float4*)(wrow + idx), w);
        }
    }
}

extern "C" void kernel_launch(void* const* d_in, const int* in_sizes, int n_in,
                              void* d_out, int out_size) {
    const float* q     = (const float*)d_in[0];
    const float* k     = (const float*)d_in[1];
    const float* v     = (const float*)d_in[2];
    const float* prev  = (const float*)d_in[3];
    const float* mask  = (const float*)d_in[4];
    const float* scale = (const float*)d_in[5];

    float* out  = (float*)d_out;
    float* wout = out  + (long)8 * 16 * 1024 * 64;
    float* sout = wout + (long)8 * 16 * 1024 * 1024;

    cudaFuncSetAttribute(attn_fused,
                         cudaFuncAttributeMaxDynamicSharedMemorySize, SM_TOTAL);
    attn_fused<<<8 * 16 * 8, THREADS, SM_TOTAL>>>(
        q, k, v, prev, mask, scale, out, wout, sout);
}